// round 1
// baseline (speedup 1.0000x reference)
#include <cuda_runtime.h>

// Problem constants (fixed by the reference):
//   G=1024 groups, K=16 agents/group, T=32, D=64, N=G*K=16384
//   out[n,t,0:64]  = group mean of h over the 16 agents of n's group
//   out[n,t,64:128]= h[n,t,:],  h = fc2(relu(LN(fc1(x))))
#define GRP   1024
#define AG    16
#define TT    32
#define DD    64
#define ROWSG 512          // rows per group = AG*TT
#define TILE_R 64          // rows per tile
#define N_TILES 8
#define XSTR  68           // padded smem stride for activation tiles

__device__ __forceinline__ void fma4(const float4 a,
                                     const float4 b0, const float4 b1,
                                     const float4 b2, const float4 b3,
                                     float* cr) {
    cr[0] = fmaf(a.x, b0.x, fmaf(a.y, b1.x, fmaf(a.z, b2.x, fmaf(a.w, b3.x, cr[0]))));
    cr[1] = fmaf(a.x, b0.y, fmaf(a.y, b1.y, fmaf(a.z, b2.y, fmaf(a.w, b3.y, cr[1]))));
    cr[2] = fmaf(a.x, b0.z, fmaf(a.y, b1.z, fmaf(a.z, b2.z, fmaf(a.w, b3.z, cr[2]))));
    cr[3] = fmaf(a.x, b0.w, fmaf(a.y, b1.w, fmaf(a.z, b2.w, fmaf(a.w, b3.w, cr[3]))));
}

// 64x64 @ 64x64 tile GEMM: act [64 rows x 64 d] (stride XSTR), w transposed [d][j] (stride 64).
__device__ __forceinline__ void mm_tile(const float* __restrict__ act,
                                        const float* __restrict__ wt,
                                        int r0, int j0, float c[4][4]) {
    #pragma unroll
    for (int d4 = 0; d4 < 16; d4++) {
        const float4 a0 = *(const float4*)(act + (r0 + 0) * XSTR + d4 * 4);
        const float4 a1 = *(const float4*)(act + (r0 + 1) * XSTR + d4 * 4);
        const float4 a2 = *(const float4*)(act + (r0 + 2) * XSTR + d4 * 4);
        const float4 a3 = *(const float4*)(act + (r0 + 3) * XSTR + d4 * 4);
        const float4 b0 = *(const float4*)(wt + (d4 * 4 + 0) * DD + j0);
        const float4 b1 = *(const float4*)(wt + (d4 * 4 + 1) * DD + j0);
        const float4 b2 = *(const float4*)(wt + (d4 * 4 + 2) * DD + j0);
        const float4 b3 = *(const float4*)(wt + (d4 * 4 + 3) * DD + j0);
        fma4(a0, b0, b1, b2, b3, c[0]);
        fma4(a1, b0, b1, b2, b3, c[1]);
        fma4(a2, b0, b1, b2, b3, c[2]);
        fma4(a3, b0, b1, b2, b3, c[3]);
    }
}

__global__ void __launch_bounds__(256)
subgraph_fused_kernel(const float* __restrict__ x,
                      const float* __restrict__ w1g, const float* __restrict__ b1g,
                      const float* __restrict__ lnwg, const float* __restrict__ lnbg,
                      const float* __restrict__ w2g, const float* __restrict__ b2g,
                      float* __restrict__ out) {
    extern __shared__ float sm[];
    float* xs   = sm;                        // TILE_R * XSTR = 4352
    float* hs   = xs + TILE_R * XSTR;        // 4352
    float* w1s  = hs + TILE_R * XSTR;        // 4096, transposed [d][j]
    float* w2s  = w1s + DD * DD;             // 4096, transposed [d][j]
    float* sums = w2s + DD * DD;             // TT*DD = 2048
    float* b1s  = sums + TT * DD;            // 64
    float* b2s  = b1s + DD;                  // 64
    float* lnws = b2s + DD;                  // 64
    float* lnbs = lnws + DD;                 // 64

    const int tid = threadIdx.x;
    const int g   = blockIdx.x;

    // ---- stage weights (transposed), biases; zero group sums ----
    #pragma unroll
    for (int v = 0; v < 16; v++) {
        int lin = tid + v * 256;             // 0..4095, coalesced gmem read
        int j = lin >> 6, d = lin & 63;
        w1s[d * DD + j] = w1g[lin];
        w2s[d * DD + j] = w2g[lin];
    }
    if (tid < DD) {
        b1s[tid] = b1g[tid];  b2s[tid] = b2g[tid];
        lnws[tid] = lnwg[tid]; lnbs[tid] = lnbg[tid];
    }
    #pragma unroll
    for (int v = 0; v < 8; v++) sums[tid + v * 256] = 0.f;
    __syncthreads();

    const int TX = tid & 15;                 // output-column block
    const int TY = tid >> 4;                 // output-row block
    const int j0 = TX * 4;
    const int r0 = TY * 4;

    const float* xg   = x + (size_t)g * (ROWSG * DD);
    float*       outg = out + (size_t)g * (ROWSG * 2 * DD);

    for (int it = 0; it < N_TILES; ++it) {
        // ---- stage x tile (contiguous 64x64 block) ----
        const float4* xt = (const float4*)(xg + it * TILE_R * DD);
        #pragma unroll
        for (int v = 0; v < 4; v++) {
            int lin = tid + v * 256;         // float4 index 0..1023
            int row = lin >> 4, c4 = (lin & 15) << 2;
            *(float4*)(xs + row * XSTR + c4) = xt[lin];
        }
        __syncthreads();

        // ---- GEMM1: h1 = x @ w1^T + b1 ----
        float c[4][4];
        #pragma unroll
        for (int i = 0; i < 4; i++)
            #pragma unroll
            for (int jj = 0; jj < 4; jj++) c[i][jj] = 0.f;
        mm_tile(xs, w1s, r0, j0, c);
        #pragma unroll
        for (int i = 0; i < 4; i++) {
            float4 v;
            v.x = c[i][0] + b1s[j0 + 0];
            v.y = c[i][1] + b1s[j0 + 1];
            v.z = c[i][2] + b1s[j0 + 2];
            v.w = c[i][3] + b1s[j0 + 3];
            *(float4*)(hs + (r0 + i) * XSTR + j0) = v;
        }
        __syncthreads();

        // ---- LayerNorm + ReLU (4 lanes per row, 16 elems each) -> xs ----
        {
            int row   = tid >> 2;
            int dbase = (tid & 3) * 16;
            const float* hr = hs + row * XSTR + dbase;
            float4 v0 = *(const float4*)(hr + 0);
            float4 v1 = *(const float4*)(hr + 4);
            float4 v2 = *(const float4*)(hr + 8);
            float4 v3 = *(const float4*)(hr + 12);
            float s = v0.x + v0.y + v0.z + v0.w + v1.x + v1.y + v1.z + v1.w
                    + v2.x + v2.y + v2.z + v2.w + v3.x + v3.y + v3.z + v3.w;
            float q = v0.x*v0.x + v0.y*v0.y + v0.z*v0.z + v0.w*v0.w
                    + v1.x*v1.x + v1.y*v1.y + v1.z*v1.z + v1.w*v1.w
                    + v2.x*v2.x + v2.y*v2.y + v2.z*v2.z + v2.w*v2.w
                    + v3.x*v3.x + v3.y*v3.y + v3.z*v3.z + v3.w*v3.w;
            s += __shfl_xor_sync(0xffffffffu, s, 1);
            s += __shfl_xor_sync(0xffffffffu, s, 2);
            q += __shfl_xor_sync(0xffffffffu, q, 1);
            q += __shfl_xor_sync(0xffffffffu, q, 2);
            float mu  = s * (1.f / 64.f);
            float var = q * (1.f / 64.f) - mu * mu;
            float inv = rsqrtf(var + 1e-5f);
            float* xr = xs + row * XSTR + dbase;
            #pragma unroll
            for (int e = 0; e < 4; e++) {
                float4 hv = (e == 0) ? v0 : (e == 1) ? v1 : (e == 2) ? v2 : v3;
                float4 o;
                o.x = fmaxf(fmaf((hv.x - mu) * inv, lnws[dbase + e*4 + 0], lnbs[dbase + e*4 + 0]), 0.f);
                o.y = fmaxf(fmaf((hv.y - mu) * inv, lnws[dbase + e*4 + 1], lnbs[dbase + e*4 + 1]), 0.f);
                o.z = fmaxf(fmaf((hv.z - mu) * inv, lnws[dbase + e*4 + 2], lnbs[dbase + e*4 + 2]), 0.f);
                o.w = fmaxf(fmaf((hv.w - mu) * inv, lnws[dbase + e*4 + 3], lnbs[dbase + e*4 + 3]), 0.f);
                *(float4*)(xr + e * 4) = o;
            }
        }
        __syncthreads();

        // ---- GEMM2: h = act @ w2^T + b2; write h half, stage for group sums ----
        #pragma unroll
        for (int i = 0; i < 4; i++)
            #pragma unroll
            for (int jj = 0; jj < 4; jj++) c[i][jj] = 0.f;
        mm_tile(xs, w2s, r0, j0, c);
        #pragma unroll
        for (int i = 0; i < 4; i++) {
            float4 v;
            v.x = c[i][0] + b2s[j0 + 0];
            v.y = c[i][1] + b2s[j0 + 1];
            v.z = c[i][2] + b2s[j0 + 2];
            v.w = c[i][3] + b2s[j0 + 3];
            *(float4*)(hs + (r0 + i) * XSTR + j0) = v;
            int r = it * TILE_R + r0 + i;                   // == k*32 + t
            *(float4*)(outg + (size_t)r * (2 * DD) + DD + j0) = v;
        }
        __syncthreads();

        // ---- accumulate group sums: tile holds agents {2it, 2it+1}, t=0..31 ----
        #pragma unroll
        for (int v = 0; v < 2; v++) {
            int f  = tid + v * 256;                          // float4 index 0..511
            int t  = f >> 4, c4 = (f & 15) << 2;
            float4 a = *(const float4*)(hs + t * XSTR + c4);
            float4 b = *(const float4*)(hs + (t + 32) * XSTR + c4);
            float4 s = *(const float4*)(sums + t * DD + c4);
            s.x += a.x + b.x; s.y += a.y + b.y;
            s.z += a.z + b.z; s.w += a.w + b.w;
            *(float4*)(sums + t * DD + c4) = s;
        }
        __syncthreads();
    }

    // ---- write group means to the first half for all 16 agents ----
    #pragma unroll
    for (int v = 0; v < 2; v++) {
        int f  = tid + v * 256;
        int t  = f >> 4, c4 = (f & 15) << 2;
        float4 s = *(const float4*)(sums + t * DD + c4);
        s.x *= 0.0625f; s.y *= 0.0625f; s.z *= 0.0625f; s.w *= 0.0625f;
        #pragma unroll
        for (int k = 0; k < AG; k++)
            *(float4*)(outg + (size_t)(k * TT + t) * (2 * DD) + c4) = s;
    }
}

extern "C" void kernel_launch(void* const* d_in, const int* in_sizes, int n_in,
                              void* d_out, int out_size) {
    const float* x    = (const float*)d_in[0];
    // d_in[1] batch_traffic_id_map (groups are contiguous, implied by n>>4)
    // d_in[2] num_traffics (constant 16)
    const float* fc1w = (const float*)d_in[3];
    const float* fc1b = (const float*)d_in[4];
    const float* lnw  = (const float*)d_in[5];
    const float* lnb  = (const float*)d_in[6];
    const float* fc2w = (const float*)d_in[7];
    const float* fc2b = (const float*)d_in[8];
    float* out = (float*)d_out;

    const int smem_bytes = (2 * TILE_R * XSTR + 2 * DD * DD + TT * DD + 4 * DD) * (int)sizeof(float); // 76800
    cudaFuncSetAttribute(subgraph_fused_kernel,
                         cudaFuncAttributeMaxDynamicSharedMemorySize, smem_bytes);
    subgraph_fused_kernel<<<GRP, 256, smem_bytes>>>(x, fc1w, fc1b, lnw, lnb, fc2w, fc2b, out);
}